// round 2
// baseline (speedup 1.0000x reference)
#include <cuda_runtime.h>

// Problem constants
#define Bb 16
#define Ss 1024
#define Ee 512
#define Hh 8
#define Dd 64
#define Ll 4
#define SD (Ss*Dd)          // 65536
#define EE (Ee*Ee)          // 262144
#define Mtot (Bb*Ss)        // 16384

// Scratch (device globals; no allocation allowed)
__device__ float g_Q[Bb*Hh*Ss*Dd];      // (B,H,S,D)
__device__ float g_K[Bb*Hh*Ss*Dd];
__device__ float g_V[Bb*Hh*Ss*Dd];
__device__ float g_concat[Bb*Ss*Ee];    // (B,S,E)
__device__ float g_Wv[EE];
__device__ float g_Wo[EE];
__device__ float g_bv[Ee];
__device__ float g_bo[Ee];

// ---------------------------------------------------------------------------
// Fuse language-specific weights: Wv = Wv_share * Wv_spec[lang], etc.
// ---------------------------------------------------------------------------
__global__ void fuse_weights(const float* __restrict__ Wv_sh, const float* __restrict__ Wv_sp,
                             const float* __restrict__ bv_sh, const float* __restrict__ bv_sp,
                             const float* __restrict__ Wo_sh, const float* __restrict__ Wo_sp,
                             const float* __restrict__ bo_sh, const float* __restrict__ bo_sp,
                             const int* __restrict__ langp) {
    int lang = langp[0];
    int i = blockIdx.x * blockDim.x + threadIdx.x;
    if (i < EE) {
        g_Wv[i] = Wv_sh[i] * Wv_sp[(size_t)lang * EE + i];
        g_Wo[i] = Wo_sh[i] * Wo_sp[(size_t)lang * EE + i];
    }
    if (i < Ee) {
        g_bv[i] = bv_sh[i] + bv_sp[lang * Ee + i];
        g_bo[i] = bo_sh[i] + bo_sp[lang * Ee + i];
    }
}

// ---------------------------------------------------------------------------
// SGEMM: C[m,n] = (sum_k A[m,k]*Bw[n,k] + bias[n]) * scale
// A: (Mtot, 512) row-major.  Bw: (512, 512) row-major (torch Linear: out,in).
// BM=BN=128, BK=8, 256 threads, 8x8 micro-tile, double-buffered smem.
// MODE 0: C row-major (Mtot, 512)   (output projection -> d_out)
// MODE 1: C scattered to (B,H,S,D)  (Q/K/V projections)
// ---------------------------------------------------------------------------
template<int MODE>
__global__ __launch_bounds__(256, 2)
void gemm128(const float* __restrict__ A, const float* __restrict__ Bw,
             const float* __restrict__ bias, float* __restrict__ C, float scale) {
    const int K = Ee;
    __shared__ float As[2][8][128];
    __shared__ float Bs[2][8][128];

    int tid = threadIdx.x;
    int m0 = blockIdx.x * 128, n0 = blockIdx.y * 128;

    // global loader mapping: 256 threads load a 128x8 tile as float4
    int lrow = tid >> 1;            // 0..127
    int lcol = (tid & 1) * 4;       // 0 or 4
    const float* Ap = A  + (size_t)(m0 + lrow) * K + lcol;
    const float* Bp = Bw + (size_t)(n0 + lrow) * K + lcol;

    // compute mapping: 16x16 thread grid, 8x8 micro-tile
    int tx = tid & 15;              // n direction
    int ty = tid >> 4;              // m direction

    float acc[8][8] = {};
    float4 pa, pb;                  // prefetch regs

    // prologue: load k-tile 0
    pa = *(const float4*)(Ap);
    pb = *(const float4*)(Bp);
    As[0][lcol+0][lrow] = pa.x; As[0][lcol+1][lrow] = pa.y;
    As[0][lcol+2][lrow] = pa.z; As[0][lcol+3][lrow] = pa.w;
    Bs[0][lcol+0][lrow] = pb.x; Bs[0][lcol+1][lrow] = pb.y;
    Bs[0][lcol+2][lrow] = pb.z; Bs[0][lcol+3][lrow] = pb.w;
    __syncthreads();

    for (int k0 = 0; k0 < K; k0 += 8) {
        int buf = (k0 >> 3) & 1;
        // prefetch next tile into registers (overlaps compute below)
        if (k0 + 8 < K) {
            pa = *(const float4*)(Ap + k0 + 8);
            pb = *(const float4*)(Bp + k0 + 8);
        }
        #pragma unroll
        for (int kk = 0; kk < 8; kk++) {
            float4 a0 = *(const float4*)&As[buf][kk][ty * 8];
            float4 a1 = *(const float4*)&As[buf][kk][ty * 8 + 4];
            float4 b0 = *(const float4*)&Bs[buf][kk][tx * 8];
            float4 b1 = *(const float4*)&Bs[buf][kk][tx * 8 + 4];
            float am[8] = {a0.x,a0.y,a0.z,a0.w,a1.x,a1.y,a1.z,a1.w};
            float bn[8] = {b0.x,b0.y,b0.z,b0.w,b1.x,b1.y,b1.z,b1.w};
            #pragma unroll
            for (int i = 0; i < 8; i++)
                #pragma unroll
                for (int j = 0; j < 8; j++)
                    acc[i][j] += am[i] * bn[j];
        }
        if (k0 + 8 < K) {
            int nb = buf ^ 1;
            As[nb][lcol+0][lrow] = pa.x; As[nb][lcol+1][lrow] = pa.y;
            As[nb][lcol+2][lrow] = pa.z; As[nb][lcol+3][lrow] = pa.w;
            Bs[nb][lcol+0][lrow] = pb.x; Bs[nb][lcol+1][lrow] = pb.y;
            Bs[nb][lcol+2][lrow] = pb.z; Bs[nb][lcol+3][lrow] = pb.w;
            __syncthreads();
        }
    }

    #pragma unroll
    for (int i = 0; i < 8; i++) {
        int m = m0 + ty * 8 + i;
        #pragma unroll
        for (int j = 0; j < 8; j++) {
            int n = n0 + tx * 8 + j;
            float v = (acc[i][j] + bias[n]) * scale;
            if (MODE == 0) {
                C[(size_t)m * Ee + n] = v;
            } else {
                int b = m >> 10, s = m & 1023;     // S = 1024
                int h = n >> 6,  d = n & 63;       // D = 64
                g_Q[0];  // no-op keep
                C[(size_t)(b * Hh + h) * SD + s * Dd + d] = v;
            }
        }
    }
}

// ---------------------------------------------------------------------------
// Flash-style attention. One thread per query row; 128 queries per block.
// grid = (S/128, B*H). Streams K/V through smem in 64-key chunks.
// Q is pre-scaled by 1/D in the projection epilogue (the reference applies
// D^-0.5 twice), so logits are raw dot products here.
// ---------------------------------------------------------------------------
__global__ __launch_bounds__(128)
void attn_kernel(const int* __restrict__ mask) {
    __shared__ float Ks[64 * 64];
    __shared__ float Vs[64 * 64];
    __shared__ int   mk[64];

    int bh = blockIdx.y;
    int b  = bh >> 3;
    int h  = bh & 7;
    int q  = blockIdx.x * 128 + threadIdx.x;

    const float* Qp = g_Q + (size_t)bh * SD + (size_t)q * Dd;
    float qreg[64];
    #pragma unroll
    for (int d = 0; d < 64; d += 4) {
        float4 t = *(const float4*)(Qp + d);
        qreg[d] = t.x; qreg[d+1] = t.y; qreg[d+2] = t.z; qreg[d+3] = t.w;
    }
    float o[64];
    #pragma unroll
    for (int d = 0; d < 64; d++) o[d] = 0.f;
    float mx = -1e30f, l = 0.f;

    const float* Kbase = g_K + (size_t)bh * SD;
    const float* Vbase = g_V + (size_t)bh * SD;

    for (int j0 = 0; j0 < Ss; j0 += 64) {
        __syncthreads();
        const float4* Kg = (const float4*)(Kbase + j0 * 64);
        const float4* Vg = (const float4*)(Vbase + j0 * 64);
        for (int i = threadIdx.x; i < 64 * 16; i += 128) {
            ((float4*)Ks)[i] = Kg[i];
            ((float4*)Vs)[i] = Vg[i];
        }
        if (threadIdx.x < 64) mk[threadIdx.x] = mask[b * Ss + j0 + threadIdx.x];
        __syncthreads();

        #pragma unroll 1
        for (int jb = 0; jb < 64; jb += 16) {
            float s[16];
            #pragma unroll
            for (int jj = 0; jj < 16; jj += 4) {
                float a0 = 0.f, a1 = 0.f, a2 = 0.f, a3 = 0.f;
                #pragma unroll
                for (int d = 0; d < 64; d += 4) {
                    float4 k0 = *(const float4*)&Ks[(jb + jj + 0) * 64 + d];
                    float4 k1 = *(const float4*)&Ks[(jb + jj + 1) * 64 + d];
                    float4 k2 = *(const float4*)&Ks[(jb + jj + 2) * 64 + d];
                    float4 k3 = *(const float4*)&Ks[(jb + jj + 3) * 64 + d];
                    a0 += qreg[d]*k0.x + qreg[d+1]*k0.y + qreg[d+2]*k0.z + qreg[d+3]*k0.w;
                    a1 += qreg[d]*k1.x + qreg[d+1]*k1.y + qreg[d+2]*k1.z + qreg[d+3]*k1.w;
                    a2 += qreg[d]*k2.x + qreg[d+1]*k2.y + qreg[d+2]*k2.z + qreg[d+3]*k2.w;
                    a3 += qreg[d]*k3.x + qreg[d+1]*k3.y + qreg[d+2]*k3.z + qreg[d+3]*k3.w;
                }
                s[jj] = a0; s[jj+1] = a1; s[jj+2] = a2; s[jj+3] = a3;
            }
            float gm = mx;
            #pragma unroll
            for (int j = 0; j < 16; j++) {
                s[j] = mk[jb + j] ? s[j] : -1e9f;
                gm = fmaxf(gm, s[j]);
            }
            float corr = __expf(mx - gm);
            mx = gm;
            l *= corr;
            #pragma unroll
            for (int d = 0; d < 64; d++) o[d] *= corr;
            #pragma unroll
            for (int j = 0; j < 16; j++) {
                float p = __expf(s[j] - gm);
                l += p;
                const float* vrow = &Vs[(jb + j) * 64];
                #pragma unroll
                for (int d = 0; d < 64; d += 4) {
                    float4 v4 = *(const float4*)(vrow + d);
                    o[d]   += p * v4.x;
                    o[d+1] += p * v4.y;
                    o[d+2] += p * v4.z;
                    o[d+3] += p * v4.w;
                }
            }
        }
    }

    float inv = 1.f / l;
    float* outp = g_concat + (size_t)(b * Ss + q) * Ee + h * 64;
    #pragma unroll
    for (int d = 0; d < 64; d += 4) {
        float4 t = make_float4(o[d]*inv, o[d+1]*inv, o[d+2]*inv, o[d+3]*inv);
        *(float4*)(outp + d) = t;
    }
}

// ---------------------------------------------------------------------------
// Launch
// ---------------------------------------------------------------------------
extern "C" void kernel_launch(void* const* d_in, const int* in_sizes, int n_in,
                              void* d_out, int out_size) {
    const float* q     = (const float*)d_in[0];
    const float* k     = (const float*)d_in[1];
    const float* v     = (const float*)d_in[2];
    const float* Wq    = (const float*)d_in[3];
    const float* bq    = (const float*)d_in[4];
    const float* Wk    = (const float*)d_in[5];
    const float* bk    = (const float*)d_in[6];
    const float* Wv_sh = (const float*)d_in[7];
    const float* Wv_sp = (const float*)d_in[8];
    const float* bv_sh = (const float*)d_in[9];
    const float* bv_sp = (const float*)d_in[10];
    const float* Wo_sh = (const float*)d_in[11];
    const float* Wo_sp = (const float*)d_in[12];
    const float* bo_sh = (const float*)d_in[13];
    const float* bo_sp = (const float*)d_in[14];
    const int*   mask  = (const int*)d_in[15];
    const int*   lang  = (const int*)d_in[16];
    float* out = (float*)d_out;

    void *pQ, *pK, *pV, *pC, *pWv, *pWo, *pbv, *pbo;
    cudaGetSymbolAddress(&pQ,  g_Q);
    cudaGetSymbolAddress(&pK,  g_K);
    cudaGetSymbolAddress(&pV,  g_V);
    cudaGetSymbolAddress(&pC,  g_concat);
    cudaGetSymbolAddress(&pWv, g_Wv);
    cudaGetSymbolAddress(&pWo, g_Wo);
    cudaGetSymbolAddress(&pbv, g_bv);
    cudaGetSymbolAddress(&pbo, g_bo);

    // 1) fuse language-specific weights
    fuse_weights<<<(EE + 255) / 256, 256>>>(Wv_sh, Wv_sp, bv_sh, bv_sp,
                                            Wo_sh, Wo_sp, bo_sh, bo_sp, lang);

    // 2) projections -> (B,H,S,D).  Q folds the double softmax scale: 1/D = 1/64.
    dim3 gg(Mtot / 128, Ee / 128);
    gemm128<1><<<gg, 256>>>(q, Wq, bq, (float*)pQ, 1.0f / 64.0f);
    gemm128<1><<<gg, 256>>>(k, Wk, bk, (float*)pK, 1.0f);
    gemm128<1><<<gg, 256>>>(v, (const float*)pWv, (const float*)pbv, (float*)pV, 1.0f);

    // 3) attention -> concat (B,S,E)
    attn_kernel<<<dim3(Ss / 128, Bb * Hh), 128>>>(mask);

    // 4) output projection -> d_out (B,S,E)
    gemm128<0><<<gg, 256>>>((const float*)pC, (const float*)pWo, (const float*)pbo, out, 1.0f);
}

// round 13
// speedup vs baseline: 1.7394x; 1.7394x over previous
#include <cuda_runtime.h>
#include <cuda_bf16.h>
#include <cstdint>

// Problem constants
#define Bb 16
#define Ss 1024
#define Ee 512
#define Hh 8
#define Dd 64
#define SD (Ss*Dd)          // 65536
#define EE (Ee*Ee)          // 262144
#define Mtot (Bb*Ss)        // 16384

// Scratch (device globals; no allocation allowed)
__device__ float g_Q[Bb*Hh*Ss*Dd];      // (B,H,S,D)
__device__ float g_K[Bb*Hh*Ss*Dd];
__device__ float g_V[Bb*Hh*Ss*Dd];
__device__ float g_concat[Bb*Ss*Ee];    // (B,S,E)
__device__ float g_Wv[EE];
__device__ float g_Wo[EE];
__device__ float g_bv[Ee];
__device__ float g_bo[Ee];
__device__ int   g_idx[Bb*Ss];          // compacted valid-key indices per batch
__device__ int   g_cnt[Bb];             // valid-key count per batch

// ---------------------------------------------------------------------------
// Fuse language-specific weights
// ---------------------------------------------------------------------------
__global__ void fuse_weights(const float* __restrict__ Wv_sh, const float* __restrict__ Wv_sp,
                             const float* __restrict__ bv_sh, const float* __restrict__ bv_sp,
                             const float* __restrict__ Wo_sh, const float* __restrict__ Wo_sp,
                             const float* __restrict__ bo_sh, const float* __restrict__ bo_sp,
                             const int* __restrict__ langp) {
    int lang = langp[0];
    int i = blockIdx.x * blockDim.x + threadIdx.x;
    if (i < EE) {
        g_Wv[i] = Wv_sh[i] * Wv_sp[(size_t)lang * EE + i];
        g_Wo[i] = Wo_sh[i] * Wo_sp[(size_t)lang * EE + i];
    }
    if (i < Ee) {
        g_bv[i] = bv_sh[i] + bv_sp[lang * Ee + i];
        g_bo[i] = bo_sh[i] + bo_sp[lang * Ee + i];
    }
}

// ---------------------------------------------------------------------------
// Per-batch compaction of valid key indices (mask != 0)
// ---------------------------------------------------------------------------
__global__ void build_idx(const int* __restrict__ mask) {
    __shared__ int sc[Ss];
    int b = blockIdx.x, t = threadIdx.x;
    int m = mask[b * Ss + t] != 0 ? 1 : 0;
    sc[t] = m;
    __syncthreads();
    for (int off = 1; off < Ss; off <<= 1) {
        int v = (t >= off) ? sc[t - off] : 0;
        __syncthreads();
        sc[t] += v;
        __syncthreads();
    }
    int total = sc[Ss - 1];
    if (m) g_idx[b * Ss + sc[t] - 1] = t;
    if (t >= total) g_idx[b * Ss + t] = 0;   // safe padding
    if (t == 0) g_cnt[b] = total;
}

// ---------------------------------------------------------------------------
// bf16x2-split tensor-core GEMM via mma.sync (legacy HMMA; works on sm_103):
//   C[m,n] = (sum_k A[m,k]*Bw[n,k] + bias[n]) * scale
// Split each operand into bf16 hi+lo; D += Ah*Bh + Ah*Bl + Al*Bh (fp32 acc).
// BM=BN=128, BK=16, 256 threads = 8 warps (4m x 2n), warp tile 32x64.
// MODE 0: C row-major (Mtot, 512);  MODE 1: C scattered to (B,H,S,D)
// ---------------------------------------------------------------------------
#define BKP 18   // padded bf16 row stride (36B) to reduce bank conflicts

__device__ __forceinline__ void mma_bf16(float c[4], const uint32_t a[4], const uint32_t b[2]) {
    asm volatile("mma.sync.aligned.m16n8k16.row.col.f32.bf16.bf16.f32 "
                 "{%0,%1,%2,%3}, {%4,%5,%6,%7}, {%8,%9}, {%0,%1,%2,%3};"
                 : "+f"(c[0]), "+f"(c[1]), "+f"(c[2]), "+f"(c[3])
                 : "r"(a[0]), "r"(a[1]), "r"(a[2]), "r"(a[3]), "r"(b[0]), "r"(b[1]));
}

template<int MODE>
__global__ __launch_bounds__(256)
void gemm_mma(const float* __restrict__ A, const float* __restrict__ Bw,
              const float* __restrict__ bias, float* __restrict__ C, float scale) {
    __shared__ __nv_bfloat16 sAh[2][128 * BKP];
    __shared__ __nv_bfloat16 sAl[2][128 * BKP];
    __shared__ __nv_bfloat16 sBh[2][128 * BKP];
    __shared__ __nv_bfloat16 sBl[2][128 * BKP];

    int tid = threadIdx.x;
    int wid = tid >> 5, lane = tid & 31;
    int wm = wid & 3, wn = wid >> 2;         // warp grid 4(m) x 2(n)
    int g = lane >> 2, t = lane & 3;
    int m0 = blockIdx.x * 128, n0 = blockIdx.y * 128;

    // global staging: each thread handles row tid/2, k-cols (tid&1)*8 .. +8
    int srow = tid >> 1, scol = (tid & 1) * 8;
    const float* Ap = A  + (size_t)(m0 + srow) * Ee + scol;
    const float* Bp = Bw + (size_t)(n0 + srow) * Ee + scol;

    float acc[2][8][4];
    #pragma unroll
    for (int i = 0; i < 2; i++)
        #pragma unroll
        for (int j = 0; j < 8; j++)
            #pragma unroll
            for (int r = 0; r < 4; r++) acc[i][j][r] = 0.f;

    float pa[8], pb[8];

    // stage helper: hi/lo split, packed 32-bit smem stores (even element offsets)
    #define STAGE_CHUNK(BUFI) do {                                               \
        int base = srow * BKP + scol;                                            \
        _Pragma("unroll")                                                        \
        for (int j = 0; j < 8; j += 2) {                                         \
            __nv_bfloat16 h0 = __float2bfloat16(pa[j]);                          \
            __nv_bfloat16 h1 = __float2bfloat16(pa[j+1]);                        \
            __nv_bfloat16 l0 = __float2bfloat16(pa[j]   - __bfloat162float(h0)); \
            __nv_bfloat16 l1 = __float2bfloat16(pa[j+1] - __bfloat162float(h1)); \
            __nv_bfloat16 H0 = __float2bfloat16(pb[j]);                          \
            __nv_bfloat16 H1 = __float2bfloat16(pb[j+1]);                        \
            __nv_bfloat16 L0 = __float2bfloat16(pb[j]   - __bfloat162float(H0)); \
            __nv_bfloat16 L1 = __float2bfloat16(pb[j+1] - __bfloat162float(H1)); \
            *(__nv_bfloat162*)&sAh[BUFI][base + j] = __halves2bfloat162(h0, h1); \
            *(__nv_bfloat162*)&sAl[BUFI][base + j] = __halves2bfloat162(l0, l1); \
            *(__nv_bfloat162*)&sBh[BUFI][base + j] = __halves2bfloat162(H0, H1); \
            *(__nv_bfloat162*)&sBl[BUFI][base + j] = __halves2bfloat162(L0, L1); \
        }                                                                        \
    } while (0)

    // prologue: load + stage k-chunk 0
    {
        float4 a0 = *(const float4*)(Ap), a1 = *(const float4*)(Ap + 4);
        float4 b0 = *(const float4*)(Bp), b1 = *(const float4*)(Bp + 4);
        pa[0]=a0.x; pa[1]=a0.y; pa[2]=a0.z; pa[3]=a0.w; pa[4]=a1.x; pa[5]=a1.y; pa[6]=a1.z; pa[7]=a1.w;
        pb[0]=b0.x; pb[1]=b0.y; pb[2]=b0.z; pb[3]=b0.w; pb[4]=b1.x; pb[5]=b1.y; pb[6]=b1.z; pb[7]=b1.w;
        STAGE_CHUNK(0);
    }
    __syncthreads();

    for (int ks = 0; ks < 32; ks++) {        // 32 k-chunks of 16
        int buf = ks & 1;
        // prefetch next chunk to registers (overlaps MMA below)
        if (ks + 1 < 32) {
            int ko = (ks + 1) * 16;
            float4 a0 = *(const float4*)(Ap + ko), a1 = *(const float4*)(Ap + ko + 4);
            float4 b0 = *(const float4*)(Bp + ko), b1 = *(const float4*)(Bp + ko + 4);
            pa[0]=a0.x; pa[1]=a0.y; pa[2]=a0.z; pa[3]=a0.w; pa[4]=a1.x; pa[5]=a1.y; pa[6]=a1.z; pa[7]=a1.w;
            pb[0]=b0.x; pb[1]=b0.y; pb[2]=b0.z; pb[3]=b0.w; pb[4]=b1.x; pb[5]=b1.y; pb[6]=b1.z; pb[7]=b1.w;
        }

        // load fragments (m16n8k16: a0=[g][2t..], a1=[g+8][2t..], a2=[g][2t+8..], a3=[g+8][2t+8..])
        uint32_t ah[2][4], al[2][4], bh[8][2], bl[8][2];
        #pragma unroll
        for (int mt = 0; mt < 2; mt++) {
            int r = wm * 32 + mt * 16 + g;
            ah[mt][0] = *(const uint32_t*)&sAh[buf][ r      * BKP + 2*t    ];
            ah[mt][1] = *(const uint32_t*)&sAh[buf][(r + 8) * BKP + 2*t    ];
            ah[mt][2] = *(const uint32_t*)&sAh[buf][ r      * BKP + 2*t + 8];
            ah[mt][3] = *(const uint32_t*)&sAh[buf][(r + 8) * BKP + 2*t + 8];
            al[mt][0] = *(const uint32_t*)&sAl[buf][ r      * BKP + 2*t    ];
            al[mt][1] = *(const uint32_t*)&sAl[buf][(r + 8) * BKP + 2*t    ];
            al[mt][2] = *(const uint32_t*)&sAl[buf][ r      * BKP + 2*t + 8];
            al[mt][3] = *(const uint32_t*)&sAl[buf][(r + 8) * BKP + 2*t + 8];
        }
        #pragma unroll
        for (int nt = 0; nt < 8; nt++) {
            int n = wn * 64 + nt * 8 + g;
            bh[nt][0] = *(const uint32_t*)&sBh[buf][n * BKP + 2*t    ];
            bh[nt][1] = *(const uint32_t*)&sBh[buf][n * BKP + 2*t + 8];
            bl[nt][0] = *(const uint32_t*)&sBl[buf][n * BKP + 2*t    ];
            bl[nt][1] = *(const uint32_t*)&sBl[buf][n * BKP + 2*t + 8];
        }

        // 3-pass bf16 split MMA
        #pragma unroll
        for (int mt = 0; mt < 2; mt++)
            #pragma unroll
            for (int nt = 0; nt < 8; nt++) {
                mma_bf16(acc[mt][nt], ah[mt], bh[nt]);
                mma_bf16(acc[mt][nt], ah[mt], bl[nt]);
                mma_bf16(acc[mt][nt], al[mt], bh[nt]);
            }

        // stage prefetched chunk into the other buffer
        if (ks + 1 < 32) {
            int nb = buf ^ 1;
            STAGE_CHUNK(nb);
            __syncthreads();
        }
    }
    #undef STAGE_CHUNK

    // epilogue: c0=[g][2t], c1=[g][2t+1], c2=[g+8][2t], c3=[g+8][2t+1]
    #pragma unroll
    for (int mt = 0; mt < 2; mt++) {
        int m1 = m0 + wm * 32 + mt * 16 + g;
        int m2 = m1 + 8;
        #pragma unroll
        for (int nt = 0; nt < 8; nt++) {
            int n = n0 + wn * 64 + nt * 8 + 2 * t;
            float bx = bias[n], by = bias[n + 1];
            float2 v1 = make_float2((acc[mt][nt][0] + bx) * scale, (acc[mt][nt][1] + by) * scale);
            float2 v2 = make_float2((acc[mt][nt][2] + bx) * scale, (acc[mt][nt][3] + by) * scale);
            if (MODE == 0) {
                *(float2*)(C + (size_t)m1 * Ee + n) = v1;
                *(float2*)(C + (size_t)m2 * Ee + n) = v2;
            } else {
                int h = n >> 6, d = n & 63;
                int b1v = m1 >> 10, s1 = m1 & 1023;
                int b2v = m2 >> 10, s2 = m2 & 1023;
                *(float2*)(C + (size_t)(b1v * Hh + h) * SD + s1 * Dd + d) = v1;
                *(float2*)(C + (size_t)(b2v * Hh + h) * SD + s2 * Dd + d) = v2;
            }
        }
    }
}

// ---------------------------------------------------------------------------
// Flash attention over COMPACTED keys. One thread per query; 128 q per block.
// Q pre-scaled by 1/D (reference double-scales). grid=(S/128, B*H).
// Masked keys contribute exp(-1e9-m)=+0.0f exactly, so dropping them is exact.
// ---------------------------------------------------------------------------
__global__ __launch_bounds__(128)
void attn_kernel() {
    __shared__ float Ks[64 * 64];
    __shared__ float Vs[64 * 64];
    __shared__ int   si[64];

    int bh = blockIdx.y;
    int b  = bh >> 3;
    int h  = bh & 7;
    int q  = blockIdx.x * 128 + threadIdx.x;
    int cnt = g_cnt[b];

    const float* Qp = g_Q + (size_t)bh * SD + (size_t)q * Dd;
    float qreg[64];
    #pragma unroll
    for (int d = 0; d < 64; d += 4) {
        float4 t = *(const float4*)(Qp + d);
        qreg[d] = t.x; qreg[d+1] = t.y; qreg[d+2] = t.z; qreg[d+3] = t.w;
    }
    float o[64];
    #pragma unroll
    for (int d = 0; d < 64; d++) o[d] = 0.f;
    float mx = -1e30f, l = 0.f;

    const float4* K4 = (const float4*)(g_K + (size_t)bh * SD);
    const float4* V4 = (const float4*)(g_V + (size_t)bh * SD);
    const int* idxp = g_idx + b * Ss;

    for (int j0 = 0; j0 < cnt; j0 += 64) {
        __syncthreads();
        if (threadIdx.x < 64) {
            int ii = j0 + threadIdx.x;
            si[threadIdx.x] = (ii < cnt) ? idxp[ii] : 0;
        }
        __syncthreads();
        for (int i = threadIdx.x; i < 64 * 16; i += 128) {
            int row = i >> 4, col = i & 15;
            int g = si[row] * 16 + col;
            ((float4*)Ks)[i] = K4[g];
            ((float4*)Vs)[i] = V4[g];
        }
        __syncthreads();

        #pragma unroll 1
        for (int jb = 0; jb < 64; jb += 16) {
            float s[16];
            #pragma unroll
            for (int jj = 0; jj < 16; jj += 4) {
                float a0 = 0.f, a1 = 0.f, a2 = 0.f, a3 = 0.f;
                #pragma unroll
                for (int d = 0; d < 64; d += 4) {
                    float4 k0 = *(const float4*)&Ks[(jb + jj + 0) * 64 + d];
                    float4 k1 = *(const float4*)&Ks[(jb + jj + 1) * 64 + d];
                    float4 k2 = *(const float4*)&Ks[(jb + jj + 2) * 64 + d];
                    float4 k3 = *(const float4*)&Ks[(jb + jj + 3) * 64 + d];
                    a0 += qreg[d]*k0.x + qreg[d+1]*k0.y + qreg[d+2]*k0.z + qreg[d+3]*k0.w;
                    a1 += qreg[d]*k1.x + qreg[d+1]*k1.y + qreg[d+2]*k1.z + qreg[d+3]*k1.w;
                    a2 += qreg[d]*k2.x + qreg[d+1]*k2.y + qreg[d+2]*k2.z + qreg[d+3]*k2.w;
                    a3 += qreg[d]*k3.x + qreg[d+1]*k3.y + qreg[d+2]*k3.z + qreg[d+3]*k3.w;
                }
                s[jj] = a0; s[jj+1] = a1; s[jj+2] = a2; s[jj+3] = a3;
            }
            float gm = mx;
            #pragma unroll
            for (int j = 0; j < 16; j++) {
                s[j] = (j0 + jb + j < cnt) ? s[j] : -1e9f;
                gm = fmaxf(gm, s[j]);
            }
            if (gm > mx) {   // corr==1.0f exactly when max unchanged -> skip rescale
                float corr = __expf(mx - gm);
                mx = gm;
                l *= corr;
                #pragma unroll
                for (int d = 0; d < 64; d++) o[d] *= corr;
            }
            #pragma unroll
            for (int j = 0; j < 16; j++) {
                float p = __expf(s[j] - gm);
                l += p;
                const float* vrow = &Vs[(jb + j) * 64];
                #pragma unroll
                for (int d = 0; d < 64; d += 4) {
                    float4 v4 = *(const float4*)(vrow + d);
                    o[d]   += p * v4.x;
                    o[d+1] += p * v4.y;
                    o[d+2] += p * v4.z;
                    o[d+3] += p * v4.w;
                }
            }
        }
    }

    float inv = 1.f / l;
    float* outp = g_concat + (size_t)(b * Ss + q) * Ee + h * 64;
    #pragma unroll
    for (int d = 0; d < 64; d += 4) {
        float4 t = make_float4(o[d]*inv, o[d+1]*inv, o[d+2]*inv, o[d+3]*inv);
        *(float4*)(outp + d) = t;
    }
}

// ---------------------------------------------------------------------------
// Launch
// ---------------------------------------------------------------------------
extern "C" void kernel_launch(void* const* d_in, const int* in_sizes, int n_in,
                              void* d_out, int out_size) {
    const float* q     = (const float*)d_in[0];
    const float* k     = (const float*)d_in[1];
    const float* v     = (const float*)d_in[2];
    const float* Wq    = (const float*)d_in[3];
    const float* bq    = (const float*)d_in[4];
    const float* Wk    = (const float*)d_in[5];
    const float* bk    = (const float*)d_in[6];
    const float* Wv_sh = (const float*)d_in[7];
    const float* Wv_sp = (const float*)d_in[8];
    const float* bv_sh = (const float*)d_in[9];
    const float* bv_sp = (const float*)d_in[10];
    const float* Wo_sh = (const float*)d_in[11];
    const float* Wo_sp = (const float*)d_in[12];
    const float* bo_sh = (const float*)d_in[13];
    const float* bo_sp = (const float*)d_in[14];
    const int*   mask  = (const int*)d_in[15];
    const int*   lang  = (const int*)d_in[16];
    float* out = (float*)d_out;

    void *pQ, *pK, *pV, *pC, *pWv, *pWo, *pbv, *pbo;
    cudaGetSymbolAddress(&pQ,  g_Q);
    cudaGetSymbolAddress(&pK,  g_K);
    cudaGetSymbolAddress(&pV,  g_V);
    cudaGetSymbolAddress(&pC,  g_concat);
    cudaGetSymbolAddress(&pWv, g_Wv);
    cudaGetSymbolAddress(&pWo, g_Wo);
    cudaGetSymbolAddress(&pbv, g_bv);
    cudaGetSymbolAddress(&pbo, g_bo);

    // 1) fuse language-specific weights + compact mask
    fuse_weights<<<(EE + 255) / 256, 256>>>(Wv_sh, Wv_sp, bv_sh, bv_sp,
                                            Wo_sh, Wo_sp, bo_sh, bo_sp, lang);
    build_idx<<<Bb, Ss>>>(mask);

    // 2) projections -> (B,H,S,D). Q folds the double softmax scale (1/64).
    dim3 gg(Mtot / 128, Ee / 128);
    gemm_mma<1><<<gg, 256>>>(q, Wq, bq, (float*)pQ, 1.0f / 64.0f);
    gemm_mma<1><<<gg, 256>>>(k, Wk, bk, (float*)pK, 1.0f);
    gemm_mma<1><<<gg, 256>>>(v, (const float*)pWv, (const float*)pbv, (float*)pV, 1.0f);

    // 3) attention over compacted keys -> concat (B,S,E)
    attn_kernel<<<dim3(Ss / 128, Bb * Hh), 128>>>();

    // 4) output projection -> d_out
    gemm_mma<0><<<gg, 256>>>((const float*)pC, (const float*)pWo, (const float*)pbo, out, 1.0f);
}

// round 15
// speedup vs baseline: 2.7546x; 1.5837x over previous
#include <cuda_runtime.h>
#include <cuda_bf16.h>
#include <cstdint>

// Problem constants
#define Bb 16
#define Ss 1024
#define Ee 512
#define Hh 8
#define Dd 64
#define SD (Ss*Dd)          // 65536
#define EE (Ee*Ee)          // 262144
#define Mtot (Bb*Ss)        // 16384

// Scratch (device globals; no allocation allowed)
__device__ float g_Q[Bb*Hh*Ss*Dd];      // (B,H,S,D)
__device__ float g_K[Bb*Hh*Ss*Dd];
__device__ float g_V[Bb*Hh*Ss*Dd];
__device__ float g_concat[Bb*Ss*Ee];    // (B,S,E)
__device__ float g_bv[Ee];
__device__ float g_bo[Ee];
__device__ int   g_idx[Bb*Ss];
__device__ int   g_cnt[Bb];
// pre-split bf16 operands
__device__ __nv_bfloat16 g_Ah[Mtot*Ee];
__device__ __nv_bfloat16 g_Al[Mtot*Ee];
__device__ __nv_bfloat16 g_Wh[4*EE];    // 0=Wq 1=Wk 2=Wv(fused) 3=Wo(fused)
__device__ __nv_bfloat16 g_Wl[4*EE];

__device__ __forceinline__ uint32_t smem_u32(const void* p) {
    uint32_t a;
    asm("{ .reg .u64 t; cvta.to.shared.u64 t, %1; cvt.u32.u64 %0, t; }" : "=r"(a) : "l"(p));
    return a;
}
__device__ __forceinline__ void mma_bf16(float c[4], const uint32_t a[4], const uint32_t b[2]) {
    asm volatile("mma.sync.aligned.m16n8k16.row.col.f32.bf16.bf16.f32 "
                 "{%0,%1,%2,%3}, {%4,%5,%6,%7}, {%8,%9}, {%0,%1,%2,%3};"
                 : "+f"(c[0]), "+f"(c[1]), "+f"(c[2]), "+f"(c[3])
                 : "r"(a[0]), "r"(a[1]), "r"(a[2]), "r"(a[3]), "r"(b[0]), "r"(b[1]));
}
#define LDMX4(d0,d1,d2,d3,a) \
    asm volatile("ldmatrix.sync.aligned.m8n8.x4.shared.b16 {%0,%1,%2,%3},[%4];" \
                 : "=r"(d0),"=r"(d1),"=r"(d2),"=r"(d3) : "r"(a))
#define LDMX4T(d0,d1,d2,d3,a) \
    asm volatile("ldmatrix.sync.aligned.m8n8.x4.trans.shared.b16 {%0,%1,%2,%3},[%4];" \
                 : "=r"(d0),"=r"(d1),"=r"(d2),"=r"(d3) : "r"(a))

__device__ __forceinline__ uint32_t packsplit(float x, float y, uint32_t& lo) {
    __nv_bfloat16 hx = __float2bfloat16(x), hy = __float2bfloat16(y);
    __nv_bfloat16 lx = __float2bfloat16(x - __bfloat162float(hx));
    __nv_bfloat16 ly = __float2bfloat16(y - __bfloat162float(hy));
    __nv_bfloat162 l2 = __halves2bfloat162(lx, ly);
    lo = *(uint32_t*)&l2;
    __nv_bfloat162 h2 = __halves2bfloat162(hx, hy);
    return *(uint32_t*)&h2;
}

// ---------------------------------------------------------------------------
// Pre-split kernels
// ---------------------------------------------------------------------------
__global__ void split_act(const float* __restrict__ X) {
    int i = (blockIdx.x * blockDim.x + threadIdx.x) * 4;
    float4 v = *(const float4*)(X + i);
    uint32_t l0, l1;
    uint32_t h0 = packsplit(v.x, v.y, l0);
    uint32_t h1 = packsplit(v.z, v.w, l1);
    *(uint32_t*)&g_Ah[i]     = h0;  *(uint32_t*)&g_Ah[i + 2] = h1;
    *(uint32_t*)&g_Al[i]     = l0;  *(uint32_t*)&g_Al[i + 2] = l1;
}

__global__ void split_w(const float* __restrict__ Wq, const float* __restrict__ Wk,
                        const float* __restrict__ Wv_sh, const float* __restrict__ Wv_sp,
                        const float* __restrict__ bv_sh, const float* __restrict__ bv_sp,
                        const float* __restrict__ Wo_sh, const float* __restrict__ Wo_sp,
                        const float* __restrict__ bo_sh, const float* __restrict__ bo_sp,
                        const int* __restrict__ langp) {
    int lang = langp[0];
    int i = blockIdx.x * blockDim.x + threadIdx.x;
    if (i < EE) {
        float w[4];
        w[0] = Wq[i]; w[1] = Wk[i];
        w[2] = Wv_sh[i] * Wv_sp[(size_t)lang * EE + i];
        w[3] = Wo_sh[i] * Wo_sp[(size_t)lang * EE + i];
        #pragma unroll
        for (int j = 0; j < 4; j++) {
            __nv_bfloat16 h = __float2bfloat16(w[j]);
            g_Wh[j * EE + i] = h;
            g_Wl[j * EE + i] = __float2bfloat16(w[j] - __bfloat162float(h));
        }
    }
    if (i < Ee) {
        g_bv[i] = bv_sh[i] + bv_sp[lang * Ee + i];
        g_bo[i] = bo_sh[i] + bo_sp[lang * Ee + i];
    }
}

// ---------------------------------------------------------------------------
// Per-batch compaction of valid key indices (mask != 0)
// ---------------------------------------------------------------------------
__global__ void build_idx(const int* __restrict__ mask) {
    __shared__ int sc[Ss];
    int b = blockIdx.x, t = threadIdx.x;
    int m = mask[b * Ss + t] != 0 ? 1 : 0;
    sc[t] = m;
    __syncthreads();
    for (int off = 1; off < Ss; off <<= 1) {
        int v = (t >= off) ? sc[t - off] : 0;
        __syncthreads();
        sc[t] += v;
        __syncthreads();
    }
    int total = sc[Ss - 1];
    if (m) g_idx[b * Ss + sc[t] - 1] = t;
    if (t >= total) g_idx[b * Ss + t] = 0;
    if (t == 0) g_cnt[b] = total;
}

// ---------------------------------------------------------------------------
// bf16-split GEMM (pre-split operands, copy-only staging).
// BM=BN=128 BK=16, 256 thr, 8 warps 4mx2n, warp tile 32x64, BKP=24 pad.
// ---------------------------------------------------------------------------
#define BKP 24
#define GSM_ELEMS 3072            // 128*24 per (array,buf)
#define GSM_TOTAL (GSM_ELEMS*8*2) // bytes: 8 array-bufs * 2B = 49152

template<int MODE>
__global__ __launch_bounds__(256)
void gemm_mma(const __nv_bfloat16* __restrict__ Ah, const __nv_bfloat16* __restrict__ Al,
              const __nv_bfloat16* __restrict__ Wh, const __nv_bfloat16* __restrict__ Wl,
              const float* __restrict__ bias, float* __restrict__ C, float scale) {
    extern __shared__ __nv_bfloat16 sm[];
    __nv_bfloat16* sAh = sm;                 // [2][3072]
    __nv_bfloat16* sAl = sm + 2 * GSM_ELEMS;
    __nv_bfloat16* sBh = sm + 4 * GSM_ELEMS;
    __nv_bfloat16* sBl = sm + 6 * GSM_ELEMS;

    int tid = threadIdx.x;
    int wid = tid >> 5, lane = tid & 31;
    int wm = wid & 3, wn = wid >> 2;
    int g = lane >> 2, t = lane & 3;
    int m0 = blockIdx.x * 128, n0 = blockIdx.y * 128;

    int srow = tid >> 1, scol = (tid & 1) * 8;
    size_t aoff = (size_t)(m0 + srow) * Ee + scol;
    size_t boff = (size_t)(n0 + srow) * Ee + scol;
    int soff = srow * BKP + scol;

    float acc[2][8][4];
    #pragma unroll
    for (int i = 0; i < 2; i++)
        #pragma unroll
        for (int j = 0; j < 8; j++)
            #pragma unroll
            for (int r = 0; r < 4; r++) acc[i][j][r] = 0.f;

    uint4 pah, pal, pbh, pbl;
    pah = *(const uint4*)(Ah + aoff); pal = *(const uint4*)(Al + aoff);
    pbh = *(const uint4*)(Wh + boff); pbl = *(const uint4*)(Wl + boff);
    *(uint4*)&sAh[soff] = pah; *(uint4*)&sAl[soff] = pal;
    *(uint4*)&sBh[soff] = pbh; *(uint4*)&sBl[soff] = pbl;
    __syncthreads();

    for (int ks = 0; ks < 32; ks++) {
        int buf = ks & 1;
        int bbase = buf * GSM_ELEMS;
        if (ks + 1 < 32) {
            int ko = (ks + 1) * 16;
            pah = *(const uint4*)(Ah + aoff + ko); pal = *(const uint4*)(Al + aoff + ko);
            pbh = *(const uint4*)(Wh + boff + ko); pbl = *(const uint4*)(Wl + boff + ko);
        }

        uint32_t ah[2][4], al[2][4], bh[8][2], bl[8][2];
        #pragma unroll
        for (int mt = 0; mt < 2; mt++) {
            int r = wm * 32 + mt * 16 + g;
            ah[mt][0] = *(const uint32_t*)&sAh[bbase +  r      * BKP + 2*t    ];
            ah[mt][1] = *(const uint32_t*)&sAh[bbase + (r + 8) * BKP + 2*t    ];
            ah[mt][2] = *(const uint32_t*)&sAh[bbase +  r      * BKP + 2*t + 8];
            ah[mt][3] = *(const uint32_t*)&sAh[bbase + (r + 8) * BKP + 2*t + 8];
            al[mt][0] = *(const uint32_t*)&sAl[bbase +  r      * BKP + 2*t    ];
            al[mt][1] = *(const uint32_t*)&sAl[bbase + (r + 8) * BKP + 2*t    ];
            al[mt][2] = *(const uint32_t*)&sAl[bbase +  r      * BKP + 2*t + 8];
            al[mt][3] = *(const uint32_t*)&sAl[bbase + (r + 8) * BKP + 2*t + 8];
        }
        #pragma unroll
        for (int nt = 0; nt < 8; nt++) {
            int n = wn * 64 + nt * 8 + g;
            bh[nt][0] = *(const uint32_t*)&sBh[bbase + n * BKP + 2*t    ];
            bh[nt][1] = *(const uint32_t*)&sBh[bbase + n * BKP + 2*t + 8];
            bl[nt][0] = *(const uint32_t*)&sBl[bbase + n * BKP + 2*t    ];
            bl[nt][1] = *(const uint32_t*)&sBl[bbase + n * BKP + 2*t + 8];
        }

        #pragma unroll
        for (int mt = 0; mt < 2; mt++)
            #pragma unroll
            for (int nt = 0; nt < 8; nt++) {
                mma_bf16(acc[mt][nt], ah[mt], bh[nt]);
                mma_bf16(acc[mt][nt], ah[mt], bl[nt]);
                mma_bf16(acc[mt][nt], al[mt], bh[nt]);
            }

        if (ks + 1 < 32) {
            int nbase = (buf ^ 1) * GSM_ELEMS;
            *(uint4*)&sAh[nbase + soff] = pah; *(uint4*)&sAl[nbase + soff] = pal;
            *(uint4*)&sBh[nbase + soff] = pbh; *(uint4*)&sBl[nbase + soff] = pbl;
            __syncthreads();
        }
    }

    #pragma unroll
    for (int mt = 0; mt < 2; mt++) {
        int m1 = m0 + wm * 32 + mt * 16 + g;
        int m2 = m1 + 8;
        #pragma unroll
        for (int nt = 0; nt < 8; nt++) {
            int n = n0 + wn * 64 + nt * 8 + 2 * t;
            float bx = bias[n], by = bias[n + 1];
            float2 v1 = make_float2((acc[mt][nt][0] + bx) * scale, (acc[mt][nt][1] + by) * scale);
            float2 v2 = make_float2((acc[mt][nt][2] + bx) * scale, (acc[mt][nt][3] + by) * scale);
            if (MODE == 0) {
                *(float2*)(C + (size_t)m1 * Ee + n) = v1;
                *(float2*)(C + (size_t)m2 * Ee + n) = v2;
            } else {
                int h = n >> 6, d = n & 63;
                int b1v = m1 >> 10, s1 = m1 & 1023;
                int b2v = m2 >> 10, s2 = m2 & 1023;
                *(float2*)(C + (size_t)(b1v * Hh + h) * SD + s1 * Dd + d) = v1;
                *(float2*)(C + (size_t)(b2v * Hh + h) * SD + s2 * Dd + d) = v2;
            }
        }
    }
}

// ---------------------------------------------------------------------------
// Tensor-core flash attention over COMPACTED keys (bf16 3-pass split).
// Block: 64 queries x one (b,h); 4 warps, warp = 16 query rows.
// K tile [64 key][64 d] bf16 h/l; V same layout, B-frags via ldmatrix.trans.
// ---------------------------------------------------------------------------
#define AKP 72                   // bf16 row stride (144B, 16B-aligned)
#define ATILE (64*AKP)           // elems per array
#define ASM_BYTES (4*ATILE*2 + 64*64*4 + 256)

__global__ __launch_bounds__(128)
void attn_mma() {
    extern __shared__ char smraw[];
    __nv_bfloat16* sKh = (__nv_bfloat16*)smraw;
    __nv_bfloat16* sKl = sKh + ATILE;
    __nv_bfloat16* sVh = sKl + ATILE;
    __nv_bfloat16* sVl = sVh + ATILE;
    float* sQ = (float*)(sVl + ATILE);      // [64][64] f32
    int* si = (int*)(sQ + 64 * 64);

    uint32_t bKh = smem_u32(sKh), bKl = smem_u32(sKl);
    uint32_t bVh = smem_u32(sVh), bVl = smem_u32(sVl);

    int tid = threadIdx.x;
    int wid = tid >> 5, lane = tid & 31;
    int g = lane >> 2, t = lane & 3;
    int bh = blockIdx.y, b = bh >> 3, h = bh & 7;
    int q0 = blockIdx.x * 64;
    int cnt = g_cnt[b];
    const float* Qb = g_Q + (size_t)bh * SD + (size_t)q0 * Dd;
    const float* Kb = g_K + (size_t)bh * SD;
    const float* Vb = g_V + (size_t)bh * SD;
    const int* idxp = g_idx + b * Ss;

    // stage Q tile and build A-fragments (split) once
    for (int i = tid; i < 64 * 16; i += 128)
        ((float4*)sQ)[i] = ((const float4*)Qb)[i];
    __syncthreads();
    uint32_t qh[4][4], ql[4][4];
    int m0 = wid * 16;
    #pragma unroll
    for (int kc = 0; kc < 4; kc++)
        #pragma unroll
        for (int r = 0; r < 4; r++) {
            int row = m0 + g + (r & 1) * 8;
            int col = kc * 16 + 2 * t + (r >> 1) * 8;
            float2 v = *(const float2*)&sQ[row * 64 + col];
            qh[kc][r] = packsplit(v.x, v.y, ql[kc][r]);
        }

    float s[8][4];
    float o[8][4];
    #pragma unroll
    for (int j = 0; j < 8; j++)
        #pragma unroll
        for (int r = 0; r < 4; r++) o[j][r] = 0.f;
    float mx0 = -1e30f, mx1 = -1e30f, l0 = 0.f, l1 = 0.f;

    int matid = lane >> 3, mrow = lane & 7;   // ldmatrix address lane roles

    for (int kt = 0; kt * 64 < cnt; kt++) {
        __syncthreads();
        if (tid < 64) {
            int ii = kt * 64 + tid;
            si[tid] = (ii < cnt) ? idxp[ii] : 0;
        }
        __syncthreads();
        // gather + split K and V tiles ([key][d] layout)
        for (int i = tid; i < 64 * 16; i += 128) {
            int row = i >> 4, c4 = (i & 15) * 4;
            int gidx = si[row] * 64 + c4;
            float4 kv = *(const float4*)(Kb + gidx);
            float4 vv = *(const float4*)(Vb + gidx);
            int off = row * AKP + c4;
            uint32_t lo;
            *(uint32_t*)&sKh[off]     = packsplit(kv.x, kv.y, lo); *(uint32_t*)&sKl[off]     = lo;
            *(uint32_t*)&sKh[off + 2] = packsplit(kv.z, kv.w, lo); *(uint32_t*)&sKl[off + 2] = lo;
            *(uint32_t*)&sVh[off]     = packsplit(vv.x, vv.y, lo); *(uint32_t*)&sVl[off]     = lo;
            *(uint32_t*)&sVh[off + 2] = packsplit(vv.z, vv.w, lo); *(uint32_t*)&sVl[off + 2] = lo;
        }
        __syncthreads();

        // ---- S = Q Kᵀ ----
        #pragma unroll
        for (int j = 0; j < 8; j++)
            #pragma unroll
            for (int r = 0; r < 4; r++) s[j][r] = 0.f;
        #pragma unroll
        for (int kc = 0; kc < 4; kc++) {
            #pragma unroll
            for (int jp = 0; jp < 8; jp += 2) {
                uint32_t koff = (uint32_t)((8 * jp + 8 * (matid >> 1) + mrow) * AKP * 2
                                           + kc * 32 + 16 * (matid & 1));
                uint32_t h0, h1, h2, h3, lo0, lo1, lo2, lo3;
                LDMX4(h0, h1, h2, h3, bKh + koff);
                LDMX4(lo0, lo1, lo2, lo3, bKl + koff);
                { uint32_t bhv[2] = {h0, h1}, blv[2] = {lo0, lo1};
                  mma_bf16(s[jp], qh[kc], bhv); mma_bf16(s[jp], qh[kc], blv);
                  mma_bf16(s[jp], ql[kc], bhv); }
                { uint32_t bhv[2] = {h2, h3}, blv[2] = {lo2, lo3};
                  mma_bf16(s[jp+1], qh[kc], bhv); mma_bf16(s[jp+1], qh[kc], blv);
                  mma_bf16(s[jp+1], ql[kc], bhv); }
            }
        }

        // ---- mask + online softmax ----
        float tm0 = -1e30f, tm1 = -1e30f;
        #pragma unroll
        for (int j = 0; j < 8; j++) {
            int c0 = kt * 64 + 8 * j + 2 * t;
            if (c0 >= cnt)     { s[j][0] = -1e9f; s[j][2] = -1e9f; }
            if (c0 + 1 >= cnt) { s[j][1] = -1e9f; s[j][3] = -1e9f; }
            tm0 = fmaxf(tm0, fmaxf(s[j][0], s[j][1]));
            tm1 = fmaxf(tm1, fmaxf(s[j][2], s[j][3]));
        }
        tm0 = fmaxf(tm0, __shfl_xor_sync(0xffffffffu, tm0, 1));
        tm0 = fmaxf(tm0, __shfl_xor_sync(0xffffffffu, tm0, 2));
        tm1 = fmaxf(tm1, __shfl_xor_sync(0xffffffffu, tm1, 1));
        tm1 = fmaxf(tm1, __shfl_xor_sync(0xffffffffu, tm1, 2));
        float nm0 = fmaxf(mx0, tm0), nm1 = fmaxf(mx1, tm1);
        if (nm0 > mx0 || nm1 > mx1) {
            float c0 = __expf(mx0 - nm0), c1 = __expf(mx1 - nm1);
            l0 *= c0; l1 *= c1;
            #pragma unroll
            for (int j = 0; j < 8; j++) {
                o[j][0] *= c0; o[j][1] *= c0; o[j][2] *= c1; o[j][3] *= c1;
            }
            mx0 = nm0; mx1 = nm1;
        }
        float rs0 = 0.f, rs1 = 0.f;
        #pragma unroll
        for (int j = 0; j < 8; j++) {
            s[j][0] = __expf(s[j][0] - nm0); s[j][1] = __expf(s[j][1] - nm0);
            s[j][2] = __expf(s[j][2] - nm1); s[j][3] = __expf(s[j][3] - nm1);
            rs0 += s[j][0] + s[j][1]; rs1 += s[j][2] + s[j][3];
        }
        rs0 += __shfl_xor_sync(0xffffffffu, rs0, 1);
        rs0 += __shfl_xor_sync(0xffffffffu, rs0, 2);
        rs1 += __shfl_xor_sync(0xffffffffu, rs1, 1);
        rs1 += __shfl_xor_sync(0xffffffffu, rs1, 2);
        l0 += rs0; l1 += rs1;

        // ---- O += P V ----
        #pragma unroll
        for (int kc = 0; kc < 4; kc++) {
            int j0 = 2 * kc, j1 = j0 + 1;
            uint32_t ph[4], pl[4];
            ph[0] = packsplit(s[j0][0], s[j0][1], pl[0]);
            ph[1] = packsplit(s[j0][2], s[j0][3], pl[1]);
            ph[2] = packsplit(s[j1][0], s[j1][1], pl[2]);
            ph[3] = packsplit(s[j1][2], s[j1][3], pl[3]);
            #pragma unroll
            for (int jtp = 0; jtp < 8; jtp += 2) {
                uint32_t voff = (uint32_t)((16 * kc + 8 * (matid & 1) + mrow) * AKP * 2
                                           + 16 * jtp + 16 * (matid >> 1));
                uint32_t h0, h1, h2, h3, lo0, lo1, lo2, lo3;
                LDMX4T(h0, h1, h2, h3, bVh + voff);
                LDMX4T(lo0, lo1, lo2, lo3, bVl + voff);
                { uint32_t bhv[2] = {h0, h1}, blv[2] = {lo0, lo1};
                  mma_bf16(o[jtp], ph, bhv); mma_bf16(o[jtp], ph, blv);
                  mma_bf16(o[jtp], pl, bhv); }
                { uint32_t bhv[2] = {h2, h3}, blv[2] = {lo2, lo3};
                  mma_bf16(o[jtp+1], ph, bhv); mma_bf16(o[jtp+1], ph, blv);
                  mma_bf16(o[jtp+1], pl, bhv); }
            }
        }
    }

    float inv0 = 1.f / l0, inv1 = 1.f / l1;
    int m1 = q0 + m0 + g, m2 = m1 + 8;
    #pragma unroll
    for (int jt = 0; jt < 8; jt++) {
        int d = h * 64 + jt * 8 + 2 * t;
        *(float2*)(g_concat + (size_t)(b * Ss + m1) * Ee + d) =
            make_float2(o[jt][0] * inv0, o[jt][1] * inv0);
        *(float2*)(g_concat + (size_t)(b * Ss + m2) * Ee + d) =
            make_float2(o[jt][2] * inv1, o[jt][3] * inv1);
    }
}

// ---------------------------------------------------------------------------
// Launch
// ---------------------------------------------------------------------------
extern "C" void kernel_launch(void* const* d_in, const int* in_sizes, int n_in,
                              void* d_out, int out_size) {
    const float* q     = (const float*)d_in[0];
    const float* k     = (const float*)d_in[1];
    const float* v     = (const float*)d_in[2];
    const float* Wq    = (const float*)d_in[3];
    const float* bq    = (const float*)d_in[4];
    const float* Wk    = (const float*)d_in[5];
    const float* bk    = (const float*)d_in[6];
    const float* Wv_sh = (const float*)d_in[7];
    const float* Wv_sp = (const float*)d_in[8];
    const float* bv_sh = (const float*)d_in[9];
    const float* bv_sp = (const float*)d_in[10];
    const float* Wo_sh = (const float*)d_in[11];
    const float* Wo_sp = (const float*)d_in[12];
    const float* bo_sh = (const float*)d_in[13];
    const float* bo_sp = (const float*)d_in[14];
    const int*   mask  = (const int*)d_in[15];
    const int*   lang  = (const int*)d_in[16];
    float* out = (float*)d_out;

    void *pQ, *pK, *pV, *pC, *pbv, *pbo, *pAh, *pAl, *pWh, *pWl;
    cudaGetSymbolAddress(&pQ,  g_Q);
    cudaGetSymbolAddress(&pK,  g_K);
    cudaGetSymbolAddress(&pV,  g_V);
    cudaGetSymbolAddress(&pC,  g_concat);
    cudaGetSymbolAddress(&pbv, g_bv);
    cudaGetSymbolAddress(&pbo, g_bo);
    cudaGetSymbolAddress(&pAh, g_Ah);
    cudaGetSymbolAddress(&pAl, g_Al);
    cudaGetSymbolAddress(&pWh, g_Wh);
    cudaGetSymbolAddress(&pWl, g_Wl);
    const __nv_bfloat16* Ah = (const __nv_bfloat16*)pAh;
    const __nv_bfloat16* Al = (const __nv_bfloat16*)pAl;
    const __nv_bfloat16* Wh = (const __nv_bfloat16*)pWh;
    const __nv_bfloat16* Wl = (const __nv_bfloat16*)pWl;

    cudaFuncSetAttribute(gemm_mma<0>, cudaFuncAttributeMaxDynamicSharedMemorySize, GSM_TOTAL);
    cudaFuncSetAttribute(gemm_mma<1>, cudaFuncAttributeMaxDynamicSharedMemorySize, GSM_TOTAL);
    cudaFuncSetAttribute(attn_mma, cudaFuncAttributeMaxDynamicSharedMemorySize, ASM_BYTES);

    split_w<<<(EE + 255) / 256, 256>>>(Wq, Wk, Wv_sh, Wv_sp, bv_sh, bv_sp,
                                       Wo_sh, Wo_sp, bo_sh, bo_sp, lang);
    build_idx<<<Bb, Ss>>>(mask);

    dim3 gg(Mtot / 128, Ee / 128);
    int sg = Mtot * Ee / 4 / 256;   // split_act grid

    // Q (folds double softmax scale 1/64)
    split_act<<<sg, 256>>>(q);
    gemm_mma<1><<<gg, 256, GSM_TOTAL>>>(Ah, Al, Wh + 0*EE, Wl + 0*EE, bq, (float*)pQ, 1.0f/64.0f);
    // K
    split_act<<<sg, 256>>>(k);
    gemm_mma<1><<<gg, 256, GSM_TOTAL>>>(Ah, Al, Wh + 1*EE, Wl + 1*EE, bk, (float*)pK, 1.0f);
    // V
    split_act<<<sg, 256>>>(v);
    gemm_mma<1><<<gg, 256, GSM_TOTAL>>>(Ah, Al, Wh + 2*EE, Wl + 2*EE, (const float*)pbv, (float*)pV, 1.0f);

    // attention -> concat
    attn_mma<<<dim3(Ss / 64, Bb * Hh), 128, ASM_BYTES>>>();

    // output projection
    split_act<<<sg, 256>>>((const float*)pC);
    gemm_mma<0><<<gg, 256, GSM_TOTAL>>>(Ah, Al, Wh + 3*EE, Wl + 3*EE, (const float*)pbo, out, 1.0f);
}